// round 16
// baseline (speedup 1.0000x reference)
#include <cuda_runtime.h>
#include <cuda_bf16.h>
#include <cstdint>

static constexpr int N   = 256;
static constexpr int B   = 512;
static constexpr int M   = N * (N - 1) / 2;   // 32640
static constexpr int TPB = 64;                // 2 warps; warp owns 32 batches
static constexpr int SS  = 36;                // smem row stride: 16B-aligned, conflict-free
static constexpr int HBUF = 32 * SS;          // floats per 32-col half-buffer
static constexpr long long NN = (long long)N * N;

__device__ __forceinline__ float sqrt_approx(float x) {
    float r;
    asm("sqrt.approx.f32 %0, %1;" : "=f"(r) : "f"(x));
    return r;
}

// Reference step; x2 = fma(-z2, rs, z2) = z2*(1-rs) in one rounding. Identical
// to the reference wherever rs >= 0.5 (Sterbenz), covering the deep-column
// plateau; <= 1 ulp relative difference below. Chain: 8 cyc/elem.
__device__ __forceinline__ float chol_step(float z, float& rs) {
    float z2 = __fmul_rn(z, z);
    float x2 = __fmaf_rn(-z2, rs, z2);
    rs       = __fadd_rn(rs, x2);
    return copysignf(sqrt_approx(x2), z);
}

__device__ __forceinline__ uint32_t su32(const void* p) {
    return (uint32_t)__cvta_generic_to_shared(p);
}
// 4B async copy: copies szb (0 or 4) bytes, zero-fills the rest of 4.
__device__ __forceinline__ void cp4(uint32_t dst, const float* src, int szb) {
    asm volatile("cp.async.ca.shared.global [%0], [%1], 4, %2;\n"
                 :: "r"(dst), "l"(src), "r"(szb));
}
#define CP_COMMIT() asm volatile("cp.async.commit_group;\n")
#define CP_WAIT(nn) asm volatile("cp.async.wait_group %0;\n" :: "n"(nn) : "memory")

// Load one 32-column half (j0..j0+31) for 32 batch streams into buf.
// Per k: lanes read consecutive input columns -> one coalesced 128B LDGSTS.
// j0 >= i degenerates to pure zero-fill (never reads out of bounds).
__device__ __forceinline__ void cp_half(float* __restrict__ buf,
                                        const float* __restrict__ vbase,
                                        int i, int j0, int lane) {
    const int j  = j0 + lane;
    const int ok = (j < i);
    const int sz = ok ? 4 : 0;
    const float* src0 = vbase + (ok ? j : 0);
    #pragma unroll
    for (int k = 0; k < 32; ++k)
        cp4(su32(&buf[k * SS + lane]), src0 + (size_t)k * M, sz);
}

// Compute 32 columns [j0, j0+32) in place: lane = batch.
__device__ __forceinline__ void compute_half(float* __restrict__ s,
                                             int j0, int i, float& rs, int lane) {
    float v[32];
    #pragma unroll
    for (int q = 0; q < 8; ++q) {             // LDS.128: aligned (SS=36), clean banks
        float4 f = *reinterpret_cast<const float4*>(&s[lane * SS + 4 * q]);
        v[4*q] = f.x; v[4*q+1] = f.y; v[4*q+2] = f.z; v[4*q+3] = f.w;
    }
    if (j0 + 32 <= i) {                       // full half
        #pragma unroll
        for (int jj = 0; jj < 32; ++jj) v[jj] = chol_step(v[jj], rs);
    } else {                                  // mixed: scan tail, diag 1, zeros
        #pragma unroll
        for (int jj = 0; jj < 32; ++jj) {
            int j = j0 + jj;                  // uniform across warp
            if (j < i)  v[jj] = chol_step(v[jj], rs);
            else        v[jj] = (j == i) ? 1.0f : 0.0f;
        }
    }
    #pragma unroll
    for (int q = 0; q < 8; ++q)
        *reinterpret_cast<float4*>(&s[lane * SS + 4 * q]) =
            make_float4(v[4*q], v[4*q+1], v[4*q+2], v[4*q+3]);
}

__global__ void __launch_bounds__(TPB, 8)
chol_from_z_kernel(const float* __restrict__ vec, float* __restrict__ out) {
    __shared__ float sw[2 * 3 * HBUF];        // 27.6 KB: 3 rotating halves per warp

    const int i    = (N - 1) - (int)blockIdx.x;   // longest rows first
    const int wrp  = (int)threadIdx.x >> 5;
    const int lane = (int)threadIdx.x & 31;
    const int bw   = (int)blockIdx.y * TPB + wrp * 32;  // warp's batch base
    const int tri  = (i * (i - 1)) >> 1;

    const float* __restrict__ vbase = vec + (size_t)bw * M + tri;
    float* __restrict__ obase = out + ((size_t)bw * N + i) * (size_t)N;
    float* const bufs[3] = { sw + (3 * wrp + 0) * HBUF,
                             sw + (3 * wrp + 1) * HBUF,
                             sw + (3 * wrp + 2) * HBUF };

    const int nh = (i >> 5) + 1;              // 32-col halves; last is mixed
    const int nt = (nh + 1) >> 1;             // 64-col store tiles

    // ---- prologue: issue halves 0,1,2 (beyond-nh ones are pure zfill) ----
    cp_half(bufs[0], vbase, i, 0,  lane); CP_COMMIT();
    cp_half(bufs[1], vbase, i, 32, lane); CP_COMMIT();
    cp_half(bufs[2], vbase, i, 64, lane); CP_COMMIT();

    float rs = 0.0f;
    for (int t = 0; t < nt; ++t) {
        const int m0 = 2 * t, m1 = 2 * t + 1;
        float* __restrict__ sa = bufs[m0 % 3];
        float* __restrict__ sb = bufs[m1 % 3];

        CP_WAIT(2);                           // half m0 ready (m1, m0+2 in flight)
        __syncwarp();
        compute_half(sa, 32 * m0, i, rs, lane);

        const bool two = (m1 < nh);
        CP_WAIT(1);                           // half m1 ready
        __syncwarp();
        if (two) compute_half(sb, 32 * m1, i, rs, lane);
        __syncwarp();                         // store phase reads other lanes' rows

        // ---- store tile t: 256B back-to-back per stream (streaming stores) ----
        const int j0 = 64 * t;
        #pragma unroll
        for (int st = 0; st < 8; ++st) {
            int flat = lane + 32 * st;        // (batch k, quad q)
            int k = flat >> 3, q = flat & 7;
            float* dst = obase + (size_t)k * NN + j0 + 4 * q;
            float4 fa = *reinterpret_cast<const float4*>(&sa[k * SS + 4 * q]);
            __stcs(reinterpret_cast<float4*>(dst), fa);
            if (two) {
                float4 fb = *reinterpret_cast<const float4*>(&sb[k * SS + 4 * q]);
                __stcs(reinterpret_cast<float4*>(dst + 32), fb);
            }
        }

        // ---- issue halves 2t+3, 2t+4 (their buffers were stored this tile) ----
        if (t + 1 < nt) {
            cp_half(bufs[(m0 + 3) % 3], vbase, i, 32 * (m0 + 3), lane); CP_COMMIT();
            cp_half(bufs[(m1 + 3) % 3], vbase, i, 32 * (m1 + 3), lane); CP_COMMIT();
        }
    }
    CP_WAIT(0);                               // drain stragglers before exit

    // ---- pure-zero region: columns [32*nh, N), streaming float4 stores ----
    const int zs = nh << 5;
    if (zs < N) {
        const int nzq = (N - zs) >> 2;
        const float4 z4 = make_float4(0.f, 0.f, 0.f, 0.f);
        for (int k = 0; k < 32; ++k) {
            float4* o4 = reinterpret_cast<float4*>(&obase[(size_t)k * NN + zs]);
            for (int q = lane; q < nzq; q += 32)
                __stcs(&o4[q], z4);
        }
    }
}

extern "C" void kernel_launch(void* const* d_in, const int* in_sizes, int n_in,
                              void* d_out, int out_size) {
    const float* vec = (const float*)d_in[0];
    float* out = (float*)d_out;
    dim3 grid(N, B / TPB);                    // (256, 8) -> 2048 blocks, 4096 warps
    chol_from_z_kernel<<<grid, TPB>>>(vec, out);
}